// round 1
// baseline (speedup 1.0000x reference)
#include <cuda_runtime.h>
#include <cuda_bf16.h>
#include <cstdint>

// Problem constants (fixed dataset)
#define EN    500000
#define NN    100000
#define NHH   50000
#define DD    128
#define RR    500
#define NDIS  7
#define BB    512
#define NNEG  8192

// ---------------- device scratch (no allocations allowed) ----------------
__device__ float g_hA[(size_t)NHH * DD];
__device__ float g_hB[(size_t)NHH * DD];
__device__ float g_eA[(size_t)NN * DD];
__device__ float g_eB[(size_t)NN * DD];
__device__ float g_acc[(size_t)NN * DD];
__device__ int   g_cnt_h[NHH];
__device__ int   g_cnt_n[NN];
__device__ float g_inv_h[NHH];
__device__ float g_inv_n[NN];

// ---------------- helpers ----------------
__device__ __forceinline__ void red_add_v4(float* p, float4 v) {
    asm volatile("red.global.add.v4.f32 [%0], {%1,%2,%3,%4};"
                 :: "l"(p), "f"(v.x), "f"(v.y), "f"(v.z), "f"(v.w)
                 : "memory");
}

// ---------------- counts ----------------
__global__ void count_kernel(const int* __restrict__ node_idx,
                             const int* __restrict__ hedge_idx,
                             int* __restrict__ cnt_h, int* __restrict__ cnt_n) {
    int i = blockIdx.x * blockDim.x + threadIdx.x;
    if (i < EN) {
        atomicAdd(&cnt_h[hedge_idx[i]], 2);   // hedge target appears twice (node + rel rows)
        atomicAdd(&cnt_n[node_idx[i]], 1);
    }
}

__global__ void inv_kernel(const int* __restrict__ cnt, float* __restrict__ inv, int n) {
    int i = blockIdx.x * blockDim.x + threadIdx.x;
    if (i < n) {
        int c = cnt[i];
        inv[i] = 1.0f / (float)(c > 1 ? c : 1);
    }
}

// ---------------- scatter: V2E ----------------
// For each incidence e: acc[hedge_idx[e]] += tbl[srow(e)] + rel[edge_attr[e]]
// k0 != 0 -> srow = v_dis[node_idx[e]] (tbl = dis_embedding); else srow = node_idx[e] (tbl = ent_emb)
__global__ void v2e_scatter(const int* __restrict__ node_idx,
                            const int* __restrict__ hedge_idx,
                            const int* __restrict__ edge_attr,
                            const int* __restrict__ v_dis,
                            const float* __restrict__ tbl,
                            const float* __restrict__ rel,
                            float* __restrict__ acc, int k0) {
    int gw = (blockIdx.x * blockDim.x + threadIdx.x) >> 5;
    int lane = threadIdx.x & 31;
    if (gw >= EN) return;
    int n = node_idx[gw];
    int srow = k0 ? v_dis[n] : n;
    float4 a = ((const float4*)(tbl + (size_t)srow * DD))[lane];
    float4 b = ((const float4*)(rel + (size_t)edge_attr[gw] * DD))[lane];
    a.x += b.x; a.y += b.y; a.z += b.z; a.w += b.w;
    red_add_v4(acc + (size_t)hedge_idx[gw] * DD + lane * 4, a);
}

// ---------------- scatter: E2V ----------------
__global__ void e2v_scatter(const int* __restrict__ node_idx,
                            const int* __restrict__ hedge_idx,
                            const float* __restrict__ hemb,
                            float* __restrict__ acc) {
    int gw = (blockIdx.x * blockDim.x + threadIdx.x) >> 5;
    int lane = threadIdx.x & 31;
    if (gw >= EN) return;
    float4 a = ((const float4*)(hemb + (size_t)hedge_idx[gw] * DD))[lane];
    red_add_v4(acc + (size_t)node_idx[gw] * DD + lane * 4, a);
}

// ---------------- fused transform ----------------
// out[r,:] = relu( (acc[r,:]*inv[r]) @ W1 + old[r,:] @ W2 ),  W2/old may be null
// 64-row x 128-col tile per block, 256 threads, each thread 4x8 outputs.
__global__ void transform_kernel(const float* __restrict__ acc,
                                 const float* __restrict__ inv_cnt,
                                 const float* __restrict__ oldemb,
                                 const float* __restrict__ W1,
                                 const float* __restrict__ W2,
                                 float* __restrict__ out, int M) {
    __shared__ float Ws[32 * 128];
    __shared__ float As[64 * 33];

    const int tx = threadIdx.x;
    const int row0 = blockIdx.x * 64;
    const int rg = tx >> 4;          // 0..15 -> rows rg*4 .. rg*4+3
    const int cg = (tx & 15) * 8;    // column start

    float C[4][8];
#pragma unroll
    for (int i = 0; i < 4; i++)
#pragma unroll
        for (int j = 0; j < 8; j++) C[i][j] = 0.0f;

    for (int pass = 0; pass < 2; pass++) {
        if (pass && W2 == nullptr) break;
        const float* W = pass ? W2 : W1;
        const float* Am = pass ? oldemb : acc;

        for (int kk = 0; kk < 128; kk += 32) {
            __syncthreads();
            // load W chunk [32 x 128]
#pragma unroll
            for (int i = 0; i < 4; i++) {
                int idx = tx + i * 256;         // 0..1023 float4 slots
                int r = idx >> 5;               // row 0..31
                int c = idx & 31;               // float4 col
                float4 v = ((const float4*)(W + (size_t)(kk + r) * 128))[c];
                *(float4*)&Ws[r * 128 + c * 4] = v;
            }
            // load A chunk [64 x 32] (scaled on pass 0)
#pragma unroll
            for (int i = 0; i < 2; i++) {
                int idx = tx + i * 256;         // 0..511 float4 slots
                int r = idx >> 3;               // row 0..63
                int c = idx & 7;                // float4 col within 32
                int grow = row0 + r;
                float4 v = make_float4(0.f, 0.f, 0.f, 0.f);
                if (grow < M) {
                    v = ((const float4*)(Am + (size_t)grow * 128 + kk))[c];
                    if (!pass) {
                        float s = inv_cnt[grow];
                        v.x *= s; v.y *= s; v.z *= s; v.w *= s;
                    }
                }
                float* dst = &As[r * 33 + c * 4];
                dst[0] = v.x; dst[1] = v.y; dst[2] = v.z; dst[3] = v.w;
            }
            __syncthreads();
#pragma unroll
            for (int k = 0; k < 32; k++) {
                float w[8];
#pragma unroll
                for (int j = 0; j < 8; j++) w[j] = Ws[k * 128 + cg + j];
#pragma unroll
                for (int i = 0; i < 4; i++) {
                    float a = As[(rg * 4 + i) * 33 + k];
#pragma unroll
                    for (int j = 0; j < 8; j++) C[i][j] = fmaf(a, w[j], C[i][j]);
                }
            }
        }
    }

    // epilogue: relu + store
#pragma unroll
    for (int i = 0; i < 4; i++) {
        int grow = row0 + rg * 4 + i;
        if (grow < M) {
#pragma unroll
            for (int j = 0; j < 8; j += 4) {
                float4 v;
                v.x = fmaxf(C[i][j + 0], 0.f);
                v.y = fmaxf(C[i][j + 1], 0.f);
                v.z = fmaxf(C[i][j + 2], 0.f);
                v.w = fmaxf(C[i][j + 3], 0.f);
                *(float4*)&out[(size_t)grow * 128 + cg + j] = v;
            }
        }
    }
}

// ---------------- final gather ----------------
__global__ void gather_out(const float* __restrict__ hA,
                           const float* __restrict__ eB,
                           const int* __restrict__ srcH,
                           const int* __restrict__ pos,
                           const int* __restrict__ neg,
                           float* __restrict__ out) {
    int gw = (blockIdx.x * blockDim.x + threadIdx.x) >> 5;
    int lane = threadIdx.x & 31;
    const int TOT = BB + BB + NNEG;
    if (gw >= TOT) return;
    const float* src;
    if (gw < BB)             src = hA + (size_t)srcH[gw] * DD;
    else if (gw < 2 * BB)    src = eB + (size_t)pos[gw - BB] * DD;
    else                     src = eB + (size_t)neg[gw - 2 * BB] * DD;
    ((float4*)out)[(size_t)gw * 32 + lane] = ((const float4*)src)[lane];
}

// ---------------- launch ----------------
extern "C" void kernel_launch(void* const* d_in, const int* in_sizes, int n_in,
                              void* d_out, int out_size) {
    const int* node_idx  = (const int*)d_in[0];
    const int* hedge_idx = (const int*)d_in[1];
    const int* edge_attr = (const int*)d_in[2];
    const int* v_dis     = (const int*)d_in[3];
    const int* src_h     = (const int*)d_in[4];
    const int* pos_ids   = (const int*)d_in[5];
    const int* neg_ids   = (const int*)d_in[6];
    const float* dis_emb = (const float*)d_in[7];
    const float* rel_emb = (const float*)d_in[8];
    const float* Wv_src  = (const float*)d_in[9];
    const float* Wv_self = (const float*)d_in[10];
    const float* We_src  = (const float*)d_in[11];
    const float* We_self = (const float*)d_in[12];
    float* out = (float*)d_out;

    float *hA, *hB, *eA, *eB, *acc, *invh, *invn;
    int *cnth, *cntn;
    cudaGetSymbolAddress((void**)&hA,   g_hA);
    cudaGetSymbolAddress((void**)&hB,   g_hB);
    cudaGetSymbolAddress((void**)&eA,   g_eA);
    cudaGetSymbolAddress((void**)&eB,   g_eB);
    cudaGetSymbolAddress((void**)&acc,  g_acc);
    cudaGetSymbolAddress((void**)&cnth, g_cnt_h);
    cudaGetSymbolAddress((void**)&cntn, g_cnt_n);
    cudaGetSymbolAddress((void**)&invh, g_inv_h);
    cudaGetSymbolAddress((void**)&invn, g_inv_n);

    const size_t DDsz = (size_t)DD * DD;   // weight matrix stride (elements)
    const int EW  = (EN * 32 + 255) / 256;           // edge-warp grid
    const int NHB = (NHH + 63) / 64;
    const int NB  = (NN + 63) / 64;
    const int OW  = ((BB + BB + NNEG) * 32 + 255) / 256;

    // counts (recomputed every call; deterministic)
    cudaMemsetAsync(cnth, 0, NHH * sizeof(int));
    cudaMemsetAsync(cntn, 0, NN * sizeof(int));
    count_kernel<<<(EN + 255) / 256, 256>>>(node_idx, hedge_idx, cnth, cntn);
    inv_kernel<<<(NHH + 255) / 256, 256>>>(cnth, invh, NHH);
    inv_kernel<<<(NN + 255) / 256, 256>>>(cntn, invn, NN);

    // ---- k = 0 ----
    cudaMemsetAsync(acc, 0, (size_t)NHH * DD * sizeof(float));
    v2e_scatter<<<EW, 256>>>(node_idx, hedge_idx, edge_attr, v_dis, dis_emb, rel_emb, acc, 1);
    transform_kernel<<<NHB, 256>>>(acc, invh, nullptr, Wv_src, nullptr, hA, NHH);

    cudaMemsetAsync(acc, 0, (size_t)NN * DD * sizeof(float));
    e2v_scatter<<<EW, 256>>>(node_idx, hedge_idx, hA, acc);
    transform_kernel<<<NB, 256>>>(acc, invn, nullptr, We_src, nullptr, eA, NN);

    // ---- k = 1 ----
    cudaMemsetAsync(acc, 0, (size_t)NHH * DD * sizeof(float));
    v2e_scatter<<<EW, 256>>>(node_idx, hedge_idx, edge_attr, v_dis, eA, rel_emb, acc, 0);
    transform_kernel<<<NHB, 256>>>(acc, invh, hA, Wv_src + DDsz, Wv_self + DDsz, hB, NHH);

    cudaMemsetAsync(acc, 0, (size_t)NN * DD * sizeof(float));
    e2v_scatter<<<EW, 256>>>(node_idx, hedge_idx, hB, acc);
    transform_kernel<<<NB, 256>>>(acc, invn, eA, We_src + DDsz, We_self + DDsz, eB, NN);

    // ---- k = 2 ----
    cudaMemsetAsync(acc, 0, (size_t)NHH * DD * sizeof(float));
    v2e_scatter<<<EW, 256>>>(node_idx, hedge_idx, edge_attr, v_dis, eB, rel_emb, acc, 0);
    transform_kernel<<<NHB, 256>>>(acc, invh, hB, Wv_src + 2 * DDsz, Wv_self + 2 * DDsz, hA, NHH);

    // ---- outputs: (h_out, pos_ent, neg_ent) ----
    gather_out<<<OW, 256>>>(hA, eB, src_h, pos_ids, neg_ids, out);
}

// round 3
// speedup vs baseline: 1.4053x; 1.4053x over previous
#include <cuda_runtime.h>
#include <cuda_bf16.h>
#include <cstdint>

// Problem constants (fixed dataset)
#define EN    500000
#define NN    100000
#define NHH   50000
#define DD    128
#define BB    512
#define NNEG  8192

// ---------------- device scratch ----------------
__device__ float g_hA[(size_t)NHH * DD];
__device__ float g_hB[(size_t)NHH * DD];
__device__ float g_eA[(size_t)NN * DD];
__device__ float g_eB[(size_t)NN * DD];
__device__ float g_acc[(size_t)NN * DD];
__device__ int   g_cnt_h[NHH];
__device__ int   g_cnt_n[NN];
__device__ float g_inv_h[NHH];
__device__ float g_inv_n[NN];
__device__ float g_Wh[128 * 256];
__device__ float g_Wl[128 * 256];

// ---------------- helpers ----------------
__device__ __forceinline__ void tf32_split(float x, float& h, float& l) {
    uint32_t hb;
    asm("cvt.rna.tf32.f32 %0, %1;" : "=r"(hb) : "f"(x));
    h = __uint_as_float(hb);
    float r = x - h;
    uint32_t lb;
    asm("cvt.rna.tf32.f32 %0, %1;" : "=r"(lb) : "f"(r));
    l = __uint_as_float(lb);
}

__device__ __forceinline__ void red_add_v4(float* p, float4 v) {
    asm volatile("red.global.add.v4.f32 [%0], {%1,%2,%3,%4};"
                 :: "l"(p), "f"(v.x), "f"(v.y), "f"(v.z), "f"(v.w) : "memory");
}

#define MMA_TF32(c, a, b) \
    asm volatile("mma.sync.aligned.m16n8k8.row.col.f32.tf32.tf32.f32 " \
        "{%0,%1,%2,%3}, {%4,%5,%6,%7}, {%8,%9}, {%0,%1,%2,%3};" \
        : "+f"((c)[0]), "+f"((c)[1]), "+f"((c)[2]), "+f"((c)[3]) \
        : "r"((a)[0]), "r"((a)[1]), "r"((a)[2]), "r"((a)[3]), \
          "r"((b)[0]), "r"((b)[1]))

// ---------------- counts ----------------
__global__ void count_kernel(const int* __restrict__ node_idx,
                             const int* __restrict__ hedge_idx,
                             int* __restrict__ cnt_h, int* __restrict__ cnt_n) {
    int i = blockIdx.x * blockDim.x + threadIdx.x;
    if (i < EN) {
        atomicAdd(&cnt_h[hedge_idx[i]], 2);
        atomicAdd(&cnt_n[node_idx[i]], 1);
    }
}
__global__ void inv_kernel(const int* __restrict__ cnt, float* __restrict__ inv, int n) {
    int i = blockIdx.x * blockDim.x + threadIdx.x;
    if (i < n) {
        int c = cnt[i];
        inv[i] = 1.0f / (float)(c > 1 ? c : 1);
    }
}

// ---------------- scatters ----------------
__global__ void v2e_scatter(const int* __restrict__ node_idx,
                            const int* __restrict__ hedge_idx,
                            const int* __restrict__ edge_attr,
                            const int* __restrict__ v_dis,
                            const float* __restrict__ tbl,
                            const float* __restrict__ rel,
                            float* __restrict__ acc, int k0) {
    int gw = (blockIdx.x * blockDim.x + threadIdx.x) >> 5;
    int lane = threadIdx.x & 31;
    if (gw >= EN) return;
    int n = node_idx[gw];
    int srow = k0 ? v_dis[n] : n;
    float4 a = ((const float4*)(tbl + (size_t)srow * DD))[lane];
    float4 b = ((const float4*)(rel + (size_t)edge_attr[gw] * DD))[lane];
    a.x += b.x; a.y += b.y; a.z += b.z; a.w += b.w;
    red_add_v4(acc + (size_t)hedge_idx[gw] * DD + lane * 4, a);
}
__global__ void e2v_scatter(const int* __restrict__ node_idx,
                            const int* __restrict__ hedge_idx,
                            const float* __restrict__ hemb,
                            float* __restrict__ acc) {
    int gw = (blockIdx.x * blockDim.x + threadIdx.x) >> 5;
    int lane = threadIdx.x & 31;
    if (gw >= EN) return;
    float4 a = ((const float4*)(hemb + (size_t)hedge_idx[gw] * DD))[lane];
    red_add_v4(acc + (size_t)node_idx[gw] * DD + lane * 4, a);
}

// ---------------- weight prep: transpose + 3xTF32 split ----------------
// Wh/Wl: [128 n-rows, Ktot k-cols]; Wh[n*Ktot+k] = tf32_hi(W[k][n]) (= .col layout for mma)
__global__ void wprep(const float* __restrict__ W1, const float* __restrict__ W2,
                      float* __restrict__ Wh, float* __restrict__ Wl, int Ktot) {
    int idx = blockIdx.x * blockDim.x + threadIdx.x;
    if (idx >= 128 * Ktot) return;
    int n = idx / Ktot, k = idx % Ktot;
    float w = (k < 128) ? W1[(size_t)k * 128 + n] : W2[(size_t)(k - 128) * 128 + n];
    float h, l;
    tf32_split(w, h, l);
    Wh[idx] = h;
    Wl[idx] = l;
}

// ---------------- tensor-core transform (mma.sync tf32, 3xTF32) ----------------
// out[r,:] = relu( (acc[r,:]*inv[r]) @ W1 + old[r,:] @ W2 )
// Block: 128 rows x 128 cols. 8 warps (4 row-groups x 2 col-groups), warp tile 32x64.
#define APAD 36
__global__ __launch_bounds__(256, 1) void transform_mma(
    const float* __restrict__ accp, const float* __restrict__ invp,
    const float* __restrict__ oldp,
    const float* __restrict__ Whp, const float* __restrict__ Wlp,
    float* __restrict__ out, int M, int Ktot)
{
    extern __shared__ float sm[];
    float* Ah = sm;                 // [128][APAD]
    float* Al = Ah + 128 * APAD;
    float* Bh = Al + 128 * APAD;    // [128 n][APAD k]
    float* Bl = Bh + 128 * APAD;

    const int tid = threadIdx.x;
    const int wid = tid >> 5, lane = tid & 31;
    const int wr = wid & 3, wc = wid >> 2;
    const int qr = lane >> 2, qc = lane & 3;
    const int row0 = blockIdx.x * 128;

    float C[2][8][4];
#pragma unroll
    for (int mf = 0; mf < 2; mf++)
#pragma unroll
        for (int nf = 0; nf < 8; nf++)
#pragma unroll
            for (int j = 0; j < 4; j++) C[mf][nf][j] = 0.0f;

    const int nch = Ktot >> 5;
    for (int ch = 0; ch < nch; ch++) {
        const int kk = ch << 5;
        const bool fromOld = (kk >= 128);
        const float* srcp = fromOld ? oldp : accp;
        const int scol = fromOld ? (kk - 128) : kk;

        __syncthreads();
        // load + split A chunk [128 x 32]
#pragma unroll
        for (int i = 0; i < 4; i++) {
            int idx = tid + i * 256;       // 0..1023
            int r = idx >> 3, c4 = idx & 7;
            int grow = row0 + r;
            float4 v = make_float4(0.f, 0.f, 0.f, 0.f);
            if (grow < M) {
                v = *(const float4*)(srcp + (size_t)grow * 128 + scol + c4 * 4);
                if (!fromOld) {
                    float s = invp[grow];
                    v.x *= s; v.y *= s; v.z *= s; v.w *= s;
                }
            }
            float h, l;
            int base = r * APAD + c4 * 4;
            tf32_split(v.x, h, l); Ah[base + 0] = h; Al[base + 0] = l;
            tf32_split(v.y, h, l); Ah[base + 1] = h; Al[base + 1] = l;
            tf32_split(v.z, h, l); Ah[base + 2] = h; Al[base + 2] = l;
            tf32_split(v.w, h, l); Ah[base + 3] = h; Al[base + 3] = l;
        }
        // load B chunk (pre-split): [128 n x 32 k]
#pragma unroll
        for (int i = 0; i < 4; i++) {
            int idx = tid + i * 256;
            int n = idx >> 3, c4 = idx & 7;
            float4 vh = *(const float4*)(Whp + (size_t)n * Ktot + kk + c4 * 4);
            float4 vl = *(const float4*)(Wlp + (size_t)n * Ktot + kk + c4 * 4);
            int base = n * APAD + c4 * 4;
            Bh[base + 0] = vh.x; Bh[base + 1] = vh.y; Bh[base + 2] = vh.z; Bh[base + 3] = vh.w;
            Bl[base + 0] = vl.x; Bl[base + 1] = vl.y; Bl[base + 2] = vl.z; Bl[base + 3] = vl.w;
        }
        __syncthreads();

#pragma unroll
        for (int ks = 0; ks < 4; ks++) {
            const int kb = ks * 8 + qc;
            uint32_t ah[2][4], al[2][4];
#pragma unroll
            for (int mf = 0; mf < 2; mf++) {
                int r0 = wr * 32 + mf * 16 + qr;
                ah[mf][0] = __float_as_uint(Ah[r0 * APAD + kb]);
                ah[mf][1] = __float_as_uint(Ah[(r0 + 8) * APAD + kb]);
                ah[mf][2] = __float_as_uint(Ah[r0 * APAD + kb + 4]);
                ah[mf][3] = __float_as_uint(Ah[(r0 + 8) * APAD + kb + 4]);
                al[mf][0] = __float_as_uint(Al[r0 * APAD + kb]);
                al[mf][1] = __float_as_uint(Al[(r0 + 8) * APAD + kb]);
                al[mf][2] = __float_as_uint(Al[r0 * APAD + kb + 4]);
                al[mf][3] = __float_as_uint(Al[(r0 + 8) * APAD + kb + 4]);
            }
            uint32_t bh[8][2], bl[8][2];
#pragma unroll
            for (int nf = 0; nf < 8; nf++) {
                int n = wc * 64 + nf * 8 + qr;
                bh[nf][0] = __float_as_uint(Bh[n * APAD + kb]);
                bh[nf][1] = __float_as_uint(Bh[n * APAD + kb + 4]);
                bl[nf][0] = __float_as_uint(Bl[n * APAD + kb]);
                bl[nf][1] = __float_as_uint(Bl[n * APAD + kb + 4]);
            }
#pragma unroll
            for (int mf = 0; mf < 2; mf++)
#pragma unroll
                for (int nf = 0; nf < 8; nf++) {
                    MMA_TF32(C[mf][nf], ah[mf], bh[nf]);
                    MMA_TF32(C[mf][nf], ah[mf], bl[nf]);
                    MMA_TF32(C[mf][nf], al[mf], bh[nf]);
                }
        }
    }

    // epilogue: relu + store
#pragma unroll
    for (int mf = 0; mf < 2; mf++) {
        int rA = row0 + wr * 32 + mf * 16 + qr;
#pragma unroll
        for (int nf = 0; nf < 8; nf++) {
            int c = wc * 64 + nf * 8 + qc * 2;
            if (rA < M) {
                float2 v;
                v.x = fmaxf(C[mf][nf][0], 0.f);
                v.y = fmaxf(C[mf][nf][1], 0.f);
                *(float2*)(out + (size_t)rA * 128 + c) = v;
            }
            if (rA + 8 < M) {
                float2 v;
                v.x = fmaxf(C[mf][nf][2], 0.f);
                v.y = fmaxf(C[mf][nf][3], 0.f);
                *(float2*)(out + (size_t)(rA + 8) * 128 + c) = v;
            }
        }
    }
}

// ---------------- final gather ----------------
__global__ void gather_out(const float* __restrict__ hA,
                           const float* __restrict__ eB,
                           const int* __restrict__ srcH,
                           const int* __restrict__ pos,
                           const int* __restrict__ neg,
                           float* __restrict__ out) {
    int gw = (blockIdx.x * blockDim.x + threadIdx.x) >> 5;
    int lane = threadIdx.x & 31;
    const int TOT = BB + BB + NNEG;
    if (gw >= TOT) return;
    const float* src;
    if (gw < BB)          src = hA + (size_t)srcH[gw] * DD;
    else if (gw < 2 * BB) src = eB + (size_t)pos[gw - BB] * DD;
    else                  src = eB + (size_t)neg[gw - 2 * BB] * DD;
    ((float4*)out)[(size_t)gw * 32 + lane] = ((const float4*)src)[lane];
}

// ---------------- launch ----------------
extern "C" void kernel_launch(void* const* d_in, const int* in_sizes, int n_in,
                              void* d_out, int out_size) {
    const int* node_idx  = (const int*)d_in[0];
    const int* hedge_idx = (const int*)d_in[1];
    const int* edge_attr = (const int*)d_in[2];
    const int* v_dis     = (const int*)d_in[3];
    const int* src_h     = (const int*)d_in[4];
    const int* pos_ids   = (const int*)d_in[5];
    const int* neg_ids   = (const int*)d_in[6];
    const float* dis_emb = (const float*)d_in[7];
    const float* rel_emb = (const float*)d_in[8];
    const float* Wv_src  = (const float*)d_in[9];
    const float* Wv_self = (const float*)d_in[10];
    const float* We_src  = (const float*)d_in[11];
    const float* We_self = (const float*)d_in[12];
    float* out = (float*)d_out;

    float *hA, *hB, *eA, *eB, *acc, *invh, *invn, *Wh, *Wl;
    int *cnth, *cntn;
    cudaGetSymbolAddress((void**)&hA,   g_hA);
    cudaGetSymbolAddress((void**)&hB,   g_hB);
    cudaGetSymbolAddress((void**)&eA,   g_eA);
    cudaGetSymbolAddress((void**)&eB,   g_eB);
    cudaGetSymbolAddress((void**)&acc,  g_acc);
    cudaGetSymbolAddress((void**)&cnth, g_cnt_h);
    cudaGetSymbolAddress((void**)&cntn, g_cnt_n);
    cudaGetSymbolAddress((void**)&invh, g_inv_h);
    cudaGetSymbolAddress((void**)&invn, g_inv_n);
    cudaGetSymbolAddress((void**)&Wh,   g_Wh);
    cudaGetSymbolAddress((void**)&Wl,   g_Wl);

    const int SMEM_TC = 4 * 128 * APAD * sizeof(float);   // 73728 B
    cudaFuncSetAttribute(transform_mma, cudaFuncAttributeMaxDynamicSharedMemorySize, SMEM_TC);

    const size_t DDsz = (size_t)DD * DD;
    const int EW  = (EN * 32 + 255) / 256;
    const int NHB = (NHH + 127) / 128;
    const int NB  = (NN + 127) / 128;
    const int OW  = ((BB + BB + NNEG) * 32 + 255) / 256;
    const int WP128 = (128 * 128 + 255) / 256;
    const int WP256 = (128 * 256 + 255) / 256;

    cudaMemsetAsync(cnth, 0, NHH * sizeof(int));
    cudaMemsetAsync(cntn, 0, NN * sizeof(int));
    count_kernel<<<(EN + 255) / 256, 256>>>(node_idx, hedge_idx, cnth, cntn);
    inv_kernel<<<(NHH + 255) / 256, 256>>>(cnth, invh, NHH);
    inv_kernel<<<(NN + 255) / 256, 256>>>(cntn, invn, NN);

    // ---- k = 0 ----
    cudaMemsetAsync(acc, 0, (size_t)NHH * DD * sizeof(float));
    v2e_scatter<<<EW, 256>>>(node_idx, hedge_idx, edge_attr, v_dis, dis_emb, rel_emb, acc, 1);
    wprep<<<WP128, 256>>>(Wv_src, nullptr, Wh, Wl, 128);
    transform_mma<<<NHB, 256, SMEM_TC>>>(acc, invh, nullptr, Wh, Wl, hA, NHH, 128);

    cudaMemsetAsync(acc, 0, (size_t)NN * DD * sizeof(float));
    e2v_scatter<<<EW, 256>>>(node_idx, hedge_idx, hA, acc);
    wprep<<<WP128, 256>>>(We_src, nullptr, Wh, Wl, 128);
    transform_mma<<<NB, 256, SMEM_TC>>>(acc, invn, nullptr, Wh, Wl, eA, NN, 128);

    // ---- k = 1 ----
    cudaMemsetAsync(acc, 0, (size_t)NHH * DD * sizeof(float));
    v2e_scatter<<<EW, 256>>>(node_idx, hedge_idx, edge_attr, v_dis, eA, rel_emb, acc, 0);
    wprep<<<WP256, 256>>>(Wv_src + DDsz, Wv_self + DDsz, Wh, Wl, 256);
    transform_mma<<<NHB, 256, SMEM_TC>>>(acc, invh, hA, Wh, Wl, hB, NHH, 256);

    cudaMemsetAsync(acc, 0, (size_t)NN * DD * sizeof(float));
    e2v_scatter<<<EW, 256>>>(node_idx, hedge_idx, hB, acc);
    wprep<<<WP256, 256>>>(We_src + DDsz, We_self + DDsz, Wh, Wl, 256);
    transform_mma<<<NB, 256, SMEM_TC>>>(acc, invn, eA, Wh, Wl, eB, NN, 256);

    // ---- k = 2 ----
    cudaMemsetAsync(acc, 0, (size_t)NHH * DD * sizeof(float));
    v2e_scatter<<<EW, 256>>>(node_idx, hedge_idx, edge_attr, v_dis, eB, rel_emb, acc, 0);
    wprep<<<WP256, 256>>>(Wv_src + 2 * DDsz, Wv_self + 2 * DDsz, Wh, Wl, 256);
    transform_mma<<<NHB, 256, SMEM_TC>>>(acc, invh, hB, Wh, Wl, hA, NHH, 256);

    // ---- outputs ----
    gather_out<<<OW, 256>>>(hA, eB, src_h, pos_ids, neg_ids, out);
}

// round 4
// speedup vs baseline: 1.8057x; 1.2849x over previous
#include <cuda_runtime.h>
#include <cuda_bf16.h>
#include <cstdint>

// Problem constants (fixed dataset)
#define EN    500000
#define NN    100000
#define NHH   50000
#define DD    128
#define BB    512
#define NNEG  8192

// ---------------- device scratch ----------------
__device__ float g_hA[(size_t)NHH * DD];
__device__ float g_hB[(size_t)NHH * DD];
__device__ float g_eA[(size_t)NN * DD];
__device__ float g_eB[(size_t)NN * DD];
__device__ float g_acc[(size_t)NN * DD];
__device__ int   g_cnt_h[NHH];
__device__ int   g_cnt_n[NN];
__device__ float g_inv_h[NHH];
__device__ float g_inv_n[NN];
__device__ unsigned g_Bh[65536];   // packed bf16x2 weights (hi), all 5 layers
__device__ unsigned g_Bl[65536];   // packed bf16x2 weights (lo)

// ---------------- helpers ----------------
__device__ __forceinline__ uint32_t smem_u32(const void* p) {
    uint32_t a;
    asm("{ .reg .u64 t; cvta.to.shared.u64 t, %1; cvt.u32.u64 %0, t; }" : "=r"(a) : "l"(p));
    return a;
}

// split float2 -> packed bf16x2 hi + packed bf16x2 lo (x.x in low half)
__device__ __forceinline__ void split2(float2 x, uint32_t& h, uint32_t& l) {
    uint32_t hp;
    asm("cvt.rn.bf16x2.f32 %0, %1, %2;" : "=r"(hp) : "f"(x.y), "f"(x.x));
    float h0 = __uint_as_float(hp << 16);
    float h1 = __uint_as_float(hp & 0xffff0000u);
    float r0 = x.x - h0, r1 = x.y - h1;
    uint32_t lp;
    asm("cvt.rn.bf16x2.f32 %0, %1, %2;" : "=r"(lp) : "f"(r1), "f"(r0));
    h = hp; l = lp;
}

__device__ __forceinline__ void cp16(uint32_t s, const void* g, int sz) {
    asm volatile("cp.async.cg.shared.global [%0], [%1], 16, %2;"
                 :: "r"(s), "l"(g), "r"(sz) : "memory");
}

__device__ __forceinline__ void red_add_v4(float* p, float4 v) {
    asm volatile("red.global.add.v4.f32 [%0], {%1,%2,%3,%4};"
                 :: "l"(p), "f"(v.x), "f"(v.y), "f"(v.z), "f"(v.w) : "memory");
}

#define MMA_BF16(c, a, b) \
    asm volatile("mma.sync.aligned.m16n8k16.row.col.f32.bf16.bf16.f32 " \
        "{%0,%1,%2,%3}, {%4,%5,%6,%7}, {%8,%9}, {%0,%1,%2,%3};" \
        : "+f"((c)[0]), "+f"((c)[1]), "+f"((c)[2]), "+f"((c)[3]) \
        : "r"((a)[0]), "r"((a)[1]), "r"((a)[2]), "r"((a)[3]), \
          "r"((b)[0]), "r"((b)[1]))

// ---------------- counts ----------------
__global__ void count_kernel(const int* __restrict__ node_idx,
                             const int* __restrict__ hedge_idx,
                             int* __restrict__ cnt_h, int* __restrict__ cnt_n) {
    int i = blockIdx.x * blockDim.x + threadIdx.x;
    if (i < EN) {
        atomicAdd(&cnt_h[hedge_idx[i]], 2);
        atomicAdd(&cnt_n[node_idx[i]], 1);
    }
}
__global__ void inv_kernel(const int* __restrict__ cnt, float* __restrict__ inv, int n) {
    int i = blockIdx.x * blockDim.x + threadIdx.x;
    if (i < n) {
        int c = cnt[i];
        inv[i] = 1.0f / (float)(c > 1 ? c : 1);
    }
}

// ---------------- scatters ----------------
__global__ void v2e_scatter(const int* __restrict__ node_idx,
                            const int* __restrict__ hedge_idx,
                            const int* __restrict__ edge_attr,
                            const int* __restrict__ v_dis,
                            const float* __restrict__ tbl,
                            const float* __restrict__ rel,
                            float* __restrict__ acc, int k0) {
    int gw = (blockIdx.x * blockDim.x + threadIdx.x) >> 5;
    int lane = threadIdx.x & 31;
    if (gw >= EN) return;
    int n = node_idx[gw];
    int srow = k0 ? v_dis[n] : n;
    float4 a = ((const float4*)(tbl + (size_t)srow * DD))[lane];
    float4 b = ((const float4*)(rel + (size_t)edge_attr[gw] * DD))[lane];
    a.x += b.x; a.y += b.y; a.z += b.z; a.w += b.w;
    red_add_v4(acc + (size_t)hedge_idx[gw] * DD + lane * 4, a);
}
__global__ void e2v_scatter(const int* __restrict__ node_idx,
                            const int* __restrict__ hedge_idx,
                            const float* __restrict__ hemb,
                            float* __restrict__ acc) {
    int gw = (blockIdx.x * blockDim.x + threadIdx.x) >> 5;
    int lane = threadIdx.x & 31;
    if (gw >= EN) return;
    float4 a = ((const float4*)(hemb + (size_t)hedge_idx[gw] * DD))[lane];
    red_add_v4(acc + (size_t)node_idx[gw] * DD + lane * 4, a);
}

// ---------------- weight prep: transpose + bf16 split + pack ----------------
// Bh/Bl: [128 n][Ktot/2 u32], element kp packs (k=2kp lo, k=2kp+1 hi) of W[k][n].
__global__ void wprep(const float* __restrict__ W1, const float* __restrict__ W2,
                      unsigned* __restrict__ Bh, unsigned* __restrict__ Bl, int Ktot) {
    int Kh = Ktot >> 1;
    int idx = blockIdx.x * blockDim.x + threadIdx.x;
    if (idx >= 128 * Kh) return;
    int n = idx / Kh, kp = idx % Kh;
    int k = kp * 2;
    const float* W = (k < 128) ? W1 : W2;
    int kk = k & 127;
    float2 x;
    x.x = W[(size_t)kk * 128 + n];
    x.y = W[(size_t)(kk + 1) * 128 + n];
    uint32_t h, l;
    split2(x, h, l);
    Bh[idx] = h;
    Bl[idx] = l;
}

// ---------------- tensor-core transform (bf16 3-term, cp.async double-buffered) ----
// out[r,:] = relu( (acc[r,:]*inv[r]) @ W1 + old[r,:] @ W2 )
// Block: 128 rows x 128 cols, 256 threads, 8 warps (4 row-groups x 2 col-groups).
#define A_STR 36
#define B_STR 20
#define A_SZ  (128 * A_STR)          // floats
#define B_SZ  (128 * B_STR)          // u32
#define STAGE (A_SZ + 2 * B_SZ)      // 4-byte words per stage
__global__ __launch_bounds__(256) void transform_mma(
    const float* __restrict__ accp, const float* __restrict__ invp,
    const float* __restrict__ oldp,
    const unsigned* __restrict__ Bhg, const unsigned* __restrict__ Blg,
    float* __restrict__ out, int M, int Ktot)
{
    extern __shared__ float sm[];
    uint32_t sbase = smem_u32(sm);
    const int tid = threadIdx.x;
    const int wid = tid >> 5, lane = tid & 31;
    const int wr = wid & 3, wc = wid >> 2;
    const int qr = lane >> 2, qc = lane & 3;
    const int row0 = blockIdx.x * 128;
    const int Kh = Ktot >> 1;

    // per-thread inv registers for the 4 accumulator rows this thread owns
    float s0[2], s1[2];
#pragma unroll
    for (int mf = 0; mf < 2; mf++) {
        int r = row0 + wr * 32 + mf * 16 + qr;
        s0[mf] = invp[min(r, M - 1)];
        s1[mf] = invp[min(r + 8, M - 1)];
    }

    float C[2][8][4];
#pragma unroll
    for (int mf = 0; mf < 2; mf++)
#pragma unroll
        for (int nf = 0; nf < 8; nf++)
#pragma unroll
            for (int j = 0; j < 4; j++) C[mf][nf][j] = 0.0f;

    const int nch = Ktot >> 5;

#define PREFETCH(CH) do { \
    int _b = (CH) & 1; \
    uint32_t _aS = sbase + (uint32_t)(_b * STAGE * 4); \
    uint32_t _bhS = _aS + A_SZ * 4; \
    uint32_t _blS = _bhS + B_SZ * 4; \
    int _kk = (CH) << 5; \
    const float* _sp = (_kk >= 128) ? oldp : accp; \
    int _sc = (_kk >= 128) ? (_kk - 128) : _kk; \
    _Pragma("unroll") \
    for (int _i = 0; _i < 4; _i++) { \
        int _idx = tid + _i * 256; \
        int _r = _idx >> 3, _c4 = _idx & 7; \
        int _gr = row0 + _r; \
        int _sz = (_gr < M) ? 16 : 0; \
        const float* _g = _sp + (size_t)min(_gr, M - 1) * 128 + _sc + _c4 * 4; \
        cp16(_aS + (uint32_t)((_r * A_STR + _c4 * 4) * 4), _g, _sz); \
    } \
    _Pragma("unroll") \
    for (int _i = 0; _i < 2; _i++) { \
        int _idx = tid + _i * 256; \
        int _n = _idx >> 2, _c4 = _idx & 3; \
        cp16(_bhS + (uint32_t)((_n * B_STR + _c4 * 4) * 4), \
             Bhg + (size_t)_n * Kh + (_kk >> 1) + _c4 * 4, 16); \
        cp16(_blS + (uint32_t)((_n * B_STR + _c4 * 4) * 4), \
             Blg + (size_t)_n * Kh + (_kk >> 1) + _c4 * 4, 16); \
    } \
} while (0)

    PREFETCH(0);
    asm volatile("cp.async.commit_group;" ::: "memory");

    for (int ch = 0; ch < nch; ch++) {
        if (ch + 1 < nch) {
            PREFETCH(ch + 1);
            asm volatile("cp.async.commit_group;" ::: "memory");
            asm volatile("cp.async.wait_group 1;" ::: "memory");
        } else {
            asm volatile("cp.async.wait_group 0;" ::: "memory");
        }
        __syncthreads();

        int b = ch & 1;
        const float* As = sm + b * STAGE;
        const unsigned* BhS = (const unsigned*)(sm + b * STAGE + A_SZ);
        const unsigned* BlS = BhS + B_SZ;
        const bool fromOld = ((ch << 5) >= 128);

#pragma unroll
        for (int ks = 0; ks < 2; ks++) {
            int kb = ks * 16 + 2 * qc;
            uint32_t ah[2][4], al[2][4];
#pragma unroll
            for (int mf = 0; mf < 2; mf++) {
                int r0 = wr * 32 + mf * 16 + qr;
                float2 x0 = *(const float2*)(As + r0 * A_STR + kb);
                float2 x1 = *(const float2*)(As + (r0 + 8) * A_STR + kb);
                float2 x2 = *(const float2*)(As + r0 * A_STR + kb + 8);
                float2 x3 = *(const float2*)(As + (r0 + 8) * A_STR + kb + 8);
                if (!fromOld) {
                    x0.x *= s0[mf]; x0.y *= s0[mf];
                    x2.x *= s0[mf]; x2.y *= s0[mf];
                    x1.x *= s1[mf]; x1.y *= s1[mf];
                    x3.x *= s1[mf]; x3.y *= s1[mf];
                }
                split2(x0, ah[mf][0], al[mf][0]);
                split2(x1, ah[mf][1], al[mf][1]);
                split2(x2, ah[mf][2], al[mf][2]);
                split2(x3, ah[mf][3], al[mf][3]);
            }
            uint32_t bh[8][2], bl[8][2];
#pragma unroll
            for (int nf = 0; nf < 8; nf++) {
                int n = wc * 64 + nf * 8 + qr;
                bh[nf][0] = BhS[n * B_STR + ks * 8 + qc];
                bh[nf][1] = BhS[n * B_STR + ks * 8 + 4 + qc];
                bl[nf][0] = BlS[n * B_STR + ks * 8 + qc];
                bl[nf][1] = BlS[n * B_STR + ks * 8 + 4 + qc];
            }
#pragma unroll
            for (int mf = 0; mf < 2; mf++)
#pragma unroll
                for (int nf = 0; nf < 8; nf++) {
                    MMA_BF16(C[mf][nf], ah[mf], bh[nf]);
                    MMA_BF16(C[mf][nf], ah[mf], bl[nf]);
                    MMA_BF16(C[mf][nf], al[mf], bh[nf]);
                }
        }
        __syncthreads();
    }

    // epilogue: relu + store
#pragma unroll
    for (int mf = 0; mf < 2; mf++) {
        int rA = row0 + wr * 32 + mf * 16 + qr;
#pragma unroll
        for (int nf = 0; nf < 8; nf++) {
            int c = wc * 64 + nf * 8 + qc * 2;
            if (rA < M) {
                float2 v;
                v.x = fmaxf(C[mf][nf][0], 0.f);
                v.y = fmaxf(C[mf][nf][1], 0.f);
                *(float2*)(out + (size_t)rA * 128 + c) = v;
            }
            if (rA + 8 < M) {
                float2 v;
                v.x = fmaxf(C[mf][nf][2], 0.f);
                v.y = fmaxf(C[mf][nf][3], 0.f);
                *(float2*)(out + (size_t)(rA + 8) * 128 + c) = v;
            }
        }
    }
}

// ---------------- final gather ----------------
__global__ void gather_out(const float* __restrict__ hA,
                           const float* __restrict__ eB,
                           const int* __restrict__ srcH,
                           const int* __restrict__ pos,
                           const int* __restrict__ neg,
                           float* __restrict__ out) {
    int gw = (blockIdx.x * blockDim.x + threadIdx.x) >> 5;
    int lane = threadIdx.x & 31;
    const int TOT = BB + BB + NNEG;
    if (gw >= TOT) return;
    const float* src;
    if (gw < BB)          src = hA + (size_t)srcH[gw] * DD;
    else if (gw < 2 * BB) src = eB + (size_t)pos[gw - BB] * DD;
    else                  src = eB + (size_t)neg[gw - 2 * BB] * DD;
    ((float4*)out)[(size_t)gw * 32 + lane] = ((const float4*)src)[lane];
}

// ---------------- launch ----------------
extern "C" void kernel_launch(void* const* d_in, const int* in_sizes, int n_in,
                              void* d_out, int out_size) {
    const int* node_idx  = (const int*)d_in[0];
    const int* hedge_idx = (const int*)d_in[1];
    const int* edge_attr = (const int*)d_in[2];
    const int* v_dis     = (const int*)d_in[3];
    const int* src_h     = (const int*)d_in[4];
    const int* pos_ids   = (const int*)d_in[5];
    const int* neg_ids   = (const int*)d_in[6];
    const float* dis_emb = (const float*)d_in[7];
    const float* rel_emb = (const float*)d_in[8];
    const float* Wv_src  = (const float*)d_in[9];
    const float* Wv_self = (const float*)d_in[10];
    const float* We_src  = (const float*)d_in[11];
    const float* We_self = (const float*)d_in[12];
    float* out = (float*)d_out;

    float *hA, *hB, *eA, *eB, *acc, *invh, *invn;
    int *cnth, *cntn;
    unsigned *Bh, *Bl;
    cudaGetSymbolAddress((void**)&hA,   g_hA);
    cudaGetSymbolAddress((void**)&hB,   g_hB);
    cudaGetSymbolAddress((void**)&eA,   g_eA);
    cudaGetSymbolAddress((void**)&eB,   g_eB);
    cudaGetSymbolAddress((void**)&acc,  g_acc);
    cudaGetSymbolAddress((void**)&cnth, g_cnt_h);
    cudaGetSymbolAddress((void**)&cntn, g_cnt_n);
    cudaGetSymbolAddress((void**)&invh, g_inv_h);
    cudaGetSymbolAddress((void**)&invn, g_inv_n);
    cudaGetSymbolAddress((void**)&Bh,   g_Bh);
    cudaGetSymbolAddress((void**)&Bl,   g_Bl);

    const int SMEM_TC = STAGE * 2 * 4;  // 77824 B
    cudaFuncSetAttribute(transform_mma, cudaFuncAttributeMaxDynamicSharedMemorySize, SMEM_TC);

    const size_t DDsz = (size_t)DD * DD;
    const int EW  = (EN * 32 + 255) / 256;
    const int NHB = (NHH + 127) / 128;
    const int NB  = (NN + 127) / 128;
    const int OW  = ((BB + BB + NNEG) * 32 + 255) / 256;

    // weight offsets in g_Bh/g_Bl (u32 elements)
    const int o0 = 0, o1 = 8192, o2 = 16384, o3 = 32768, o4 = 49152;

    // ---- weight prep (all layers up front) ----
    wprep<<<(128 * 64 + 255) / 256, 256>>>(Wv_src, nullptr, Bh + o0, Bl + o0, 128);
    wprep<<<(128 * 64 + 255) / 256, 256>>>(We_src, nullptr, Bh + o1, Bl + o1, 128);
    wprep<<<(128 * 128 + 255) / 256, 256>>>(Wv_src + DDsz, Wv_self + DDsz, Bh + o2, Bl + o2, 256);
    wprep<<<(128 * 128 + 255) / 256, 256>>>(We_src + DDsz, We_self + DDsz, Bh + o3, Bl + o3, 256);
    wprep<<<(128 * 128 + 255) / 256, 256>>>(Wv_src + 2 * DDsz, Wv_self + 2 * DDsz, Bh + o4, Bl + o4, 256);

    // ---- counts ----
    cudaMemsetAsync(cnth, 0, NHH * sizeof(int));
    cudaMemsetAsync(cntn, 0, NN * sizeof(int));
    count_kernel<<<(EN + 255) / 256, 256>>>(node_idx, hedge_idx, cnth, cntn);
    inv_kernel<<<(NHH + 255) / 256, 256>>>(cnth, invh, NHH);
    inv_kernel<<<(NN + 255) / 256, 256>>>(cntn, invn, NN);

    // ---- k = 0 ----
    cudaMemsetAsync(acc, 0, (size_t)NHH * DD * sizeof(float));
    v2e_scatter<<<EW, 256>>>(node_idx, hedge_idx, edge_attr, v_dis, dis_emb, rel_emb, acc, 1);
    transform_mma<<<NHB, 256, SMEM_TC>>>(acc, invh, nullptr, Bh + o0, Bl + o0, hA, NHH, 128);

    cudaMemsetAsync(acc, 0, (size_t)NN * DD * sizeof(float));
    e2v_scatter<<<EW, 256>>>(node_idx, hedge_idx, hA, acc);
    transform_mma<<<NB, 256, SMEM_TC>>>(acc, invn, nullptr, Bh + o1, Bl + o1, eA, NN, 128);

    // ---- k = 1 ----
    cudaMemsetAsync(acc, 0, (size_t)NHH * DD * sizeof(float));
    v2e_scatter<<<EW, 256>>>(node_idx, hedge_idx, edge_attr, v_dis, eA, rel_emb, acc, 0);
    transform_mma<<<NHB, 256, SMEM_TC>>>(acc, invh, hA, Bh + o2, Bl + o2, hB, NHH, 256);

    cudaMemsetAsync(acc, 0, (size_t)NN * DD * sizeof(float));
    e2v_scatter<<<EW, 256>>>(node_idx, hedge_idx, hB, acc);
    transform_mma<<<NB, 256, SMEM_TC>>>(acc, invn, eA, Bh + o3, Bl + o3, eB, NN, 256);

    // ---- k = 2 ----
    cudaMemsetAsync(acc, 0, (size_t)NHH * DD * sizeof(float));
    v2e_scatter<<<EW, 256>>>(node_idx, hedge_idx, edge_attr, v_dis, eB, rel_emb, acc, 0);
    transform_mma<<<NHB, 256, SMEM_TC>>>(acc, invh, hB, Bh + o4, Bl + o4, hA, NHH, 256);

    // ---- outputs ----
    gather_out<<<OW, 256>>>(hA, eB, src_h, pos_ids, neg_ids, out);
}

// round 5
// speedup vs baseline: 2.5029x; 1.3861x over previous
#include <cuda_runtime.h>
#include <cuda_bf16.h>
#include <cstdint>

// Problem constants (fixed dataset)
#define EN    500000
#define NN    100000
#define NHH   50000
#define DD    128
#define BB    512
#define NNEG  8192

// ---------------- device scratch ----------------
__device__ float g_hA[(size_t)NHH * DD];
__device__ float g_hB[(size_t)NHH * DD];
__device__ float g_eA[(size_t)NN * DD];
__device__ float g_eB[(size_t)NN * DD];
__device__ float g_acc[(size_t)NN * DD];
__device__ float g_relsum[(size_t)NHH * DD];
__device__ int   g_cnt_h[NHH];
__device__ int   g_cnt_n[NN];
__device__ int   g_off_h[NHH + 1];
__device__ int   g_off_n[NN + 1];
__device__ int   g_cur_h[NHH];
__device__ int   g_cur_n[NN];
__device__ int   g_csr_h[EN];
__device__ int   g_csr_n[EN];
__device__ int   g_bsum[256];
__device__ unsigned g_Bh[65536];   // packed bf16x2 weights (hi), all 5 layers
__device__ unsigned g_Bl[65536];   // packed bf16x2 weights (lo)

// ---------------- helpers ----------------
__device__ __forceinline__ uint32_t smem_u32(const void* p) {
    uint32_t a;
    asm("{ .reg .u64 t; cvta.to.shared.u64 t, %1; cvt.u32.u64 %0, t; }" : "=r"(a) : "l"(p));
    return a;
}
// split float2 -> packed bf16x2 hi + packed bf16x2 lo (x.x in low half)
__device__ __forceinline__ void split2(float2 x, uint32_t& h, uint32_t& l) {
    uint32_t hp;
    asm("cvt.rn.bf16x2.f32 %0, %1, %2;" : "=r"(hp) : "f"(x.y), "f"(x.x));
    float h0 = __uint_as_float(hp << 16);
    float h1 = __uint_as_float(hp & 0xffff0000u);
    float r0 = x.x - h0, r1 = x.y - h1;
    uint32_t lp;
    asm("cvt.rn.bf16x2.f32 %0, %1, %2;" : "=r"(lp) : "f"(r1), "f"(r0));
    h = hp; l = lp;
}
__device__ __forceinline__ void cp16(uint32_t s, const void* g, int sz) {
    asm volatile("cp.async.cg.shared.global [%0], [%1], 16, %2;"
                 :: "r"(s), "l"(g), "r"(sz) : "memory");
}
#define MMA_BF16(c, a, b) \
    asm volatile("mma.sync.aligned.m16n8k16.row.col.f32.bf16.bf16.f32 " \
        "{%0,%1,%2,%3}, {%4,%5,%6,%7}, {%8,%9}, {%0,%1,%2,%3};" \
        : "+f"((c)[0]), "+f"((c)[1]), "+f"((c)[2]), "+f"((c)[3]) \
        : "r"((a)[0]), "r"((a)[1]), "r"((a)[2]), "r"((a)[3]), \
          "r"((b)[0]), "r"((b)[1]))

// ---------------- CSR build ----------------
__global__ void count_kernel(const int* __restrict__ node_idx,
                             const int* __restrict__ hedge_idx,
                             int* __restrict__ cnt_h, int* __restrict__ cnt_n) {
    int i = blockIdx.x * blockDim.x + threadIdx.x;
    if (i < EN) {
        atomicAdd(&cnt_h[hedge_idx[i]], 1);
        atomicAdd(&cnt_n[node_idx[i]], 1);
    }
}

// exclusive scan, 1024 elems/block (256 thr x 4)
__global__ void scan_pass1(const int* __restrict__ cnt, int* __restrict__ off,
                           int* __restrict__ bsum, int n) {
    __shared__ int wsum[8];
    __shared__ int tot;
    int t = threadIdx.x, lane = t & 31, w = t >> 5;
    int b0 = blockIdx.x * 1024;
    int v[4], s = 0;
#pragma unroll
    for (int i = 0; i < 4; i++) {
        int idx = b0 + t * 4 + i;
        v[i] = (idx < n) ? cnt[idx] : 0;
        s += v[i];
    }
    int ps = s;
#pragma unroll
    for (int d = 1; d < 32; d <<= 1) {
        int x = __shfl_up_sync(0xffffffffu, ps, d);
        if (lane >= d) ps += x;
    }
    if (lane == 31) wsum[w] = ps;
    __syncthreads();
    if (t == 0) {
        int a = 0;
#pragma unroll
        for (int i = 0; i < 8; i++) { int x = wsum[i]; wsum[i] = a; a += x; }
        tot = a;
    }
    __syncthreads();
    if (t == 0) bsum[blockIdx.x] = tot;
    int a = wsum[w] + ps - s;  // exclusive prefix of this thread's chunk
#pragma unroll
    for (int i = 0; i < 4; i++) {
        int idx = b0 + t * 4 + i;
        if (idx < n) off[idx] = a;
        a += v[i];
    }
}
__global__ void scan_pass2(int* __restrict__ bsum, int nb, int* __restrict__ off, int n) {
    if (threadIdx.x == 0) {
        int a = 0;
        for (int i = 0; i < nb; i++) { int x = bsum[i]; bsum[i] = a; a += x; }
        off[n] = a;
    }
}
__global__ void scan_pass3(int* __restrict__ off, const int* __restrict__ bsum, int n) {
    int i = blockIdx.x * blockDim.x + threadIdx.x;
    if (i < n) off[i] += bsum[blockIdx.x >> 2];   // 4 blocks of 256 per 1024-elem scan block
}
__global__ void fill_kernel(const int* __restrict__ node_idx,
                            const int* __restrict__ hedge_idx,
                            const int* __restrict__ off_h, const int* __restrict__ off_n,
                            int* __restrict__ cur_h, int* __restrict__ cur_n,
                            int* __restrict__ csr_h, int* __restrict__ csr_n) {
    int e = blockIdx.x * blockDim.x + threadIdx.x;
    if (e < EN) {
        int h = hedge_idx[e];
        int s = atomicAdd(&cur_h[h], 1);
        csr_h[off_h[h] + s] = e;
        int n = node_idx[e];
        int t = atomicAdd(&cur_n[n], 1);
        csr_n[off_n[n] + t] = e;
    }
}

// ---------------- gather aggregations (no atomics) ----------------
// k=0: acc[h] = (sum_e dis[v_dis[node[e]]] + sum_e rel[attr[e]]) / max(2*deg,1); relsum stored
__global__ void v2e_gather_k0(const int* __restrict__ csr, const int* __restrict__ off,
                              const int* __restrict__ node_idx,
                              const int* __restrict__ edge_attr,
                              const int* __restrict__ v_dis,
                              const float* __restrict__ dis,
                              const float* __restrict__ rel,
                              float* __restrict__ relsum,
                              float* __restrict__ acc) {
    int h = (blockIdx.x * blockDim.x + threadIdx.x) >> 5;
    int lane = threadIdx.x & 31;
    if (h >= NHH) return;
    int s = off[h], e = off[h + 1];
    float4 ns = make_float4(0.f, 0.f, 0.f, 0.f);
    float4 rs = make_float4(0.f, 0.f, 0.f, 0.f);
    for (int j = s; j < e; j++) {
        int ed = __ldg(csr + j);
        int n = __ldg(node_idx + ed);
        float4 a = ((const float4*)(dis + (size_t)__ldg(v_dis + n) * DD))[lane];
        float4 b = ((const float4*)(rel + (size_t)__ldg(edge_attr + ed) * DD))[lane];
        ns.x += a.x; ns.y += a.y; ns.z += a.z; ns.w += a.w;
        rs.x += b.x; rs.y += b.y; rs.z += b.z; rs.w += b.w;
    }
    ((float4*)(relsum + (size_t)h * DD))[lane] = rs;
    int c = 2 * (e - s);
    float inv = 1.0f / (float)(c > 1 ? c : 1);
    float4 o;
    o.x = (ns.x + rs.x) * inv; o.y = (ns.y + rs.y) * inv;
    o.z = (ns.z + rs.z) * inv; o.w = (ns.w + rs.w) * inv;
    ((float4*)(acc + (size_t)h * DD))[lane] = o;
}
// k>=1: acc[h] = (sum_e ent[node[e]] + relsum[h]) / max(2*deg,1)
__global__ void v2e_gather(const int* __restrict__ csr, const int* __restrict__ off,
                           const int* __restrict__ node_idx,
                           const float* __restrict__ ent,
                           const float* __restrict__ relsum,
                           float* __restrict__ acc) {
    int h = (blockIdx.x * blockDim.x + threadIdx.x) >> 5;
    int lane = threadIdx.x & 31;
    if (h >= NHH) return;
    int s = off[h], e = off[h + 1];
    float4 sum = ((const float4*)(relsum + (size_t)h * DD))[lane];
    for (int j = s; j < e; j++) {
        int ed = __ldg(csr + j);
        int n = __ldg(node_idx + ed);
        float4 a = ((const float4*)(ent + (size_t)n * DD))[lane];
        sum.x += a.x; sum.y += a.y; sum.z += a.z; sum.w += a.w;
    }
    int c = 2 * (e - s);
    float inv = 1.0f / (float)(c > 1 ? c : 1);
    sum.x *= inv; sum.y *= inv; sum.z *= inv; sum.w *= inv;
    ((float4*)(acc + (size_t)h * DD))[lane] = sum;
}
// acc[n] = (sum_e hedge[hidx[e]]) / max(deg,1)
__global__ void e2v_gather(const int* __restrict__ csr, const int* __restrict__ off,
                           const int* __restrict__ hedge_idx,
                           const float* __restrict__ hemb,
                           float* __restrict__ acc) {
    int n = (blockIdx.x * blockDim.x + threadIdx.x) >> 5;
    int lane = threadIdx.x & 31;
    if (n >= NN) return;
    int s = off[n], e = off[n + 1];
    float4 sum = make_float4(0.f, 0.f, 0.f, 0.f);
    for (int j = s; j < e; j++) {
        int ed = __ldg(csr + j);
        int h = __ldg(hedge_idx + ed);
        float4 a = ((const float4*)(hemb + (size_t)h * DD))[lane];
        sum.x += a.x; sum.y += a.y; sum.z += a.z; sum.w += a.w;
    }
    int c = e - s;
    float inv = 1.0f / (float)(c > 1 ? c : 1);
    sum.x *= inv; sum.y *= inv; sum.z *= inv; sum.w *= inv;
    ((float4*)(acc + (size_t)n * DD))[lane] = sum;
}

// ---------------- weight prep (all 5 layers, one kernel) ----------------
// Bh/Bl: per layer [128 n][Kh u32]; element kp packs (k=2kp lo, 2kp+1 hi) of W[k][n].
__global__ void wprep_all(const float* __restrict__ Wv_src, const float* __restrict__ Wv_self,
                          const float* __restrict__ We_src, const float* __restrict__ We_self,
                          unsigned* __restrict__ Bh, unsigned* __restrict__ Bl) {
    const size_t DS = (size_t)DD * DD;
    int idx = blockIdx.x * blockDim.x + threadIdx.x;
    if (idx >= 65536) return;
    int layer, base, Kh;
    if (idx < 8192)       { layer = 0; base = 0;     Kh = 64;  }
    else if (idx < 16384) { layer = 1; base = 8192;  Kh = 64;  }
    else if (idx < 32768) { layer = 2; base = 16384; Kh = 128; }
    else if (idx < 49152) { layer = 3; base = 32768; Kh = 128; }
    else                  { layer = 4; base = 49152; Kh = 128; }
    int li = idx - base;
    int n = li / Kh, kp = li % Kh;
    int k = kp * 2;
    const float *W1, *W2;
    switch (layer) {
        case 0: W1 = Wv_src;            W2 = nullptr;            break;
        case 1: W1 = We_src;            W2 = nullptr;            break;
        case 2: W1 = Wv_src + DS;       W2 = Wv_self + DS;       break;
        case 3: W1 = We_src + DS;       W2 = We_self + DS;       break;
        default:W1 = Wv_src + 2 * DS;   W2 = Wv_self + 2 * DS;   break;
    }
    const float* W = (k < 128) ? W1 : W2;
    int kk = k & 127;
    float2 x;
    x.x = W[(size_t)kk * 128 + n];
    x.y = W[(size_t)(kk + 1) * 128 + n];
    uint32_t h, l;
    split2(x, h, l);
    Bh[idx] = h;
    Bl[idx] = l;
}

// ---------------- tensor-core transform (bf16 3-term, cp.async double-buffered) ----
// out[r,:] = relu( acc[r,:] @ W1 + old[r,:] @ W2 )   (acc pre-averaged)
#define A_STR 36
#define B_STR 20
#define A_SZ  (128 * A_STR)
#define B_SZ  (128 * B_STR)
#define STAGE (A_SZ + 2 * B_SZ)
__global__ __launch_bounds__(256) void transform_mma(
    const float* __restrict__ accp, const float* __restrict__ oldp,
    const unsigned* __restrict__ Bhg, const unsigned* __restrict__ Blg,
    float* __restrict__ out, int M, int Ktot)
{
    extern __shared__ float sm[];
    uint32_t sbase = smem_u32(sm);
    const int tid = threadIdx.x;
    const int wid = tid >> 5, lane = tid & 31;
    const int wr = wid & 3, wc = wid >> 2;
    const int qr = lane >> 2, qc = lane & 3;
    const int row0 = blockIdx.x * 128;
    const int Kh = Ktot >> 1;

    float C[2][8][4];
#pragma unroll
    for (int mf = 0; mf < 2; mf++)
#pragma unroll
        for (int nf = 0; nf < 8; nf++)
#pragma unroll
            for (int j = 0; j < 4; j++) C[mf][nf][j] = 0.0f;

    const int nch = Ktot >> 5;

#define PREFETCH(CH) do { \
    int _b = (CH) & 1; \
    uint32_t _aS = sbase + (uint32_t)(_b * STAGE * 4); \
    uint32_t _bhS = _aS + A_SZ * 4; \
    uint32_t _blS = _bhS + B_SZ * 4; \
    int _kk = (CH) << 5; \
    const float* _sp = (_kk >= 128) ? oldp : accp; \
    int _sc = (_kk >= 128) ? (_kk - 128) : _kk; \
    _Pragma("unroll") \
    for (int _i = 0; _i < 4; _i++) { \
        int _idx = tid + _i * 256; \
        int _r = _idx >> 3, _c4 = _idx & 7; \
        int _gr = row0 + _r; \
        int _sz = (_gr < M) ? 16 : 0; \
        const float* _g = _sp + (size_t)min(_gr, M - 1) * 128 + _sc + _c4 * 4; \
        cp16(_aS + (uint32_t)((_r * A_STR + _c4 * 4) * 4), _g, _sz); \
    } \
    _Pragma("unroll") \
    for (int _i = 0; _i < 2; _i++) { \
        int _idx = tid + _i * 256; \
        int _n = _idx >> 2, _c4 = _idx & 3; \
        cp16(_bhS + (uint32_t)((_n * B_STR + _c4 * 4) * 4), \
             Bhg + (size_t)_n * Kh + (_kk >> 1) + _c4 * 4, 16); \
        cp16(_blS + (uint32_t)((_n * B_STR + _c4 * 4) * 4), \
             Blg + (size_t)_n * Kh + (_kk >> 1) + _c4 * 4, 16); \
    } \
} while (0)

    PREFETCH(0);
    asm volatile("cp.async.commit_group;" ::: "memory");

    for (int ch = 0; ch < nch; ch++) {
        if (ch + 1 < nch) {
            PREFETCH(ch + 1);
            asm volatile("cp.async.commit_group;" ::: "memory");
            asm volatile("cp.async.wait_group 1;" ::: "memory");
        } else {
            asm volatile("cp.async.wait_group 0;" ::: "memory");
        }
        __syncthreads();

        int b = ch & 1;
        const float* As = sm + b * STAGE;
        const unsigned* BhS = (const unsigned*)(sm + b * STAGE + A_SZ);
        const unsigned* BlS = BhS + B_SZ;

#pragma unroll
        for (int ks = 0; ks < 2; ks++) {
            int kb = ks * 16 + 2 * qc;
            uint32_t ah[2][4], al[2][4];
#pragma unroll
            for (int mf = 0; mf < 2; mf++) {
                int r0 = wr * 32 + mf * 16 + qr;
                float2 x0 = *(const float2*)(As + r0 * A_STR + kb);
                float2 x1 = *(const float2*)(As + (r0 + 8) * A_STR + kb);
                float2 x2 = *(const float2*)(As + r0 * A_STR + kb + 8);
                float2 x3 = *(const float2*)(As + (r0 + 8) * A_STR + kb + 8);
                split2(x0, ah[mf][0], al[mf][0]);
                split2(x1, ah[mf][1], al[mf][1]);
                split2(x2, ah[mf][2], al[mf][2]);
                split2(x3, ah[mf][3], al[mf][3]);
            }
            uint32_t bh[8][2], bl[8][2];
#pragma unroll
            for (int nf = 0; nf < 8; nf++) {
                int n = wc * 64 + nf * 8 + qr;
                bh[nf][0] = BhS[n * B_STR + ks * 8 + qc];
                bh[nf][1] = BhS[n * B_STR + ks * 8 + 4 + qc];
                bl[nf][0] = BlS[n * B_STR + ks * 8 + qc];
                bl[nf][1] = BlS[n * B_STR + ks * 8 + 4 + qc];
            }
#pragma unroll
            for (int mf = 0; mf < 2; mf++)
#pragma unroll
                for (int nf = 0; nf < 8; nf++) {
                    MMA_BF16(C[mf][nf], ah[mf], bh[nf]);
                    MMA_BF16(C[mf][nf], ah[mf], bl[nf]);
                    MMA_BF16(C[mf][nf], al[mf], bh[nf]);
                }
        }
        __syncthreads();
    }

#pragma unroll
    for (int mf = 0; mf < 2; mf++) {
        int rA = row0 + wr * 32 + mf * 16 + qr;
#pragma unroll
        for (int nf = 0; nf < 8; nf++) {
            int c = wc * 64 + nf * 8 + qc * 2;
            if (rA < M) {
                float2 v;
                v.x = fmaxf(C[mf][nf][0], 0.f);
                v.y = fmaxf(C[mf][nf][1], 0.f);
                *(float2*)(out + (size_t)rA * 128 + c) = v;
            }
            if (rA + 8 < M) {
                float2 v;
                v.x = fmaxf(C[mf][nf][2], 0.f);
                v.y = fmaxf(C[mf][nf][3], 0.f);
                *(float2*)(out + (size_t)(rA + 8) * 128 + c) = v;
            }
        }
    }
}

// ---------------- final gather ----------------
__global__ void gather_out(const float* __restrict__ hA,
                           const float* __restrict__ eB,
                           const int* __restrict__ srcH,
                           const int* __restrict__ pos,
                           const int* __restrict__ neg,
                           float* __restrict__ out) {
    int gw = (blockIdx.x * blockDim.x + threadIdx.x) >> 5;
    int lane = threadIdx.x & 31;
    const int TOT = BB + BB + NNEG;
    if (gw >= TOT) return;
    const float* src;
    if (gw < BB)          src = hA + (size_t)srcH[gw] * DD;
    else if (gw < 2 * BB) src = eB + (size_t)pos[gw - BB] * DD;
    else                  src = eB + (size_t)neg[gw - 2 * BB] * DD;
    ((float4*)out)[(size_t)gw * 32 + lane] = ((const float4*)src)[lane];
}

// ---------------- launch ----------------
extern "C" void kernel_launch(void* const* d_in, const int* in_sizes, int n_in,
                              void* d_out, int out_size) {
    const int* node_idx  = (const int*)d_in[0];
    const int* hedge_idx = (const int*)d_in[1];
    const int* edge_attr = (const int*)d_in[2];
    const int* v_dis     = (const int*)d_in[3];
    const int* src_h     = (const int*)d_in[4];
    const int* pos_ids   = (const int*)d_in[5];
    const int* neg_ids   = (const int*)d_in[6];
    const float* dis_emb = (const float*)d_in[7];
    const float* rel_emb = (const float*)d_in[8];
    const float* Wv_src  = (const float*)d_in[9];
    const float* Wv_self = (const float*)d_in[10];
    const float* We_src  = (const float*)d_in[11];
    const float* We_self = (const float*)d_in[12];
    float* out = (float*)d_out;

    float *hA, *hB, *eA, *eB, *acc, *relsum;
    int *cnth, *cntn, *offh, *offn, *curh, *curn, *csrh, *csrn, *bsum;
    unsigned *Bh, *Bl;
    cudaGetSymbolAddress((void**)&hA,     g_hA);
    cudaGetSymbolAddress((void**)&hB,     g_hB);
    cudaGetSymbolAddress((void**)&eA,     g_eA);
    cudaGetSymbolAddress((void**)&eB,     g_eB);
    cudaGetSymbolAddress((void**)&acc,    g_acc);
    cudaGetSymbolAddress((void**)&relsum, g_relsum);
    cudaGetSymbolAddress((void**)&cnth,   g_cnt_h);
    cudaGetSymbolAddress((void**)&cntn,   g_cnt_n);
    cudaGetSymbolAddress((void**)&offh,   g_off_h);
    cudaGetSymbolAddress((void**)&offn,   g_off_n);
    cudaGetSymbolAddress((void**)&curh,   g_cur_h);
    cudaGetSymbolAddress((void**)&curn,   g_cur_n);
    cudaGetSymbolAddress((void**)&csrh,   g_csr_h);
    cudaGetSymbolAddress((void**)&csrn,   g_csr_n);
    cudaGetSymbolAddress((void**)&bsum,   g_bsum);
    cudaGetSymbolAddress((void**)&Bh,     g_Bh);
    cudaGetSymbolAddress((void**)&Bl,     g_Bl);

    const int SMEM_TC = STAGE * 2 * 4;
    cudaFuncSetAttribute(transform_mma, cudaFuncAttributeMaxDynamicSharedMemorySize, SMEM_TC);

    const int HW  = (NHH * 32 + 255) / 256;   // warp-per-hedge grid
    const int NW  = (NN * 32 + 255) / 256;    // warp-per-node grid
    const int NHB = (NHH + 127) / 128;
    const int NB  = (NN + 127) / 128;
    const int OW  = ((BB + BB + NNEG) * 32 + 255) / 256;
    const int o0 = 0, o1 = 8192, o2 = 16384, o3 = 32768, o4 = 49152;

    // ---- weight prep (one kernel, all 5 layers) ----
    wprep_all<<<256, 256>>>(Wv_src, Wv_self, We_src, We_self, Bh, Bl);

    // ---- CSR build ----
    cudaMemsetAsync(cnth, 0, NHH * sizeof(int));
    cudaMemsetAsync(cntn, 0, NN * sizeof(int));
    cudaMemsetAsync(curh, 0, NHH * sizeof(int));
    cudaMemsetAsync(curn, 0, NN * sizeof(int));
    count_kernel<<<(EN + 255) / 256, 256>>>(node_idx, hedge_idx, cnth, cntn);
    {
        int nbh = (NHH + 1023) / 1024;
        scan_pass1<<<nbh, 256>>>(cnth, offh, bsum, NHH);
        scan_pass2<<<1, 32>>>(bsum, nbh, offh, NHH);
        scan_pass3<<<(NHH + 255) / 256, 256>>>(offh, bsum, NHH);
    }
    {
        int nbn = (NN + 1023) / 1024;
        scan_pass1<<<nbn, 256>>>(cntn, offn, bsum + 128, NN);
        scan_pass2<<<1, 32>>>(bsum + 128, nbn, offn, NN);
        scan_pass3<<<(NN + 255) / 256, 256>>>(offn, bsum + 128, NN);
    }
    fill_kernel<<<(EN + 255) / 256, 256>>>(node_idx, hedge_idx, offh, offn,
                                           curh, curn, csrh, csrn);

    // ---- k = 0 ----
    v2e_gather_k0<<<HW, 256>>>(csrh, offh, node_idx, edge_attr, v_dis,
                               dis_emb, rel_emb, relsum, acc);
    transform_mma<<<NHB, 256, SMEM_TC>>>(acc, nullptr, Bh + o0, Bl + o0, hA, NHH, 128);

    e2v_gather<<<NW, 256>>>(csrn, offn, hedge_idx, hA, acc);
    transform_mma<<<NB, 256, SMEM_TC>>>(acc, nullptr, Bh + o1, Bl + o1, eA, NN, 128);

    // ---- k = 1 ----
    v2e_gather<<<HW, 256>>>(csrh, offh, node_idx, eA, relsum, acc);
    transform_mma<<<NHB, 256, SMEM_TC>>>(acc, hA, Bh + o2, Bl + o2, hB, NHH, 256);

    e2v_gather<<<NW, 256>>>(csrn, offn, hedge_idx, hB, acc);
    transform_mma<<<NB, 256, SMEM_TC>>>(acc, eA, Bh + o3, Bl + o3, eB, NN, 256);

    // ---- k = 2 ----
    v2e_gather<<<HW, 256>>>(csrh, offh, node_idx, eB, relsum, acc);
    transform_mma<<<NHB, 256, SMEM_TC>>>(acc, hB, Bh + o4, Bl + o4, hA, NHH, 256);

    // ---- outputs ----
    gather_out<<<OW, 256>>>(hA, eB, src_h, pos_ids, neg_ids, out);
}